// round 7
// baseline (speedup 1.0000x reference)
#include <cuda_runtime.h>
#include <cstdint>

#define SDIM 2048
#define EDIM 256
#define BDIM 8

__device__ float g_Q[BDIM * SDIM * EDIM];      // Q[b][s][f]
__device__ float g_attn[BDIM * SDIM * 16];     // 9 weights per (b,s), stride 16
__device__ float g_poolT[BDIM * SDIM * EDIM];  // pooled^T [b][s][e], tf32-rounded
__device__ float g_Wqr[EDIM * EDIM];           // Wq tf32-rounded
__device__ float g_Wor[EDIM * EDIM];           // Wo tf32-rounded

static __device__ __forceinline__ uint32_t smem_u32(const void* p) {
    uint32_t a;
    asm("{ .reg .u64 t; cvta.to.shared.u64 t, %1; cvt.u32.u64 %0, t; }" : "=r"(a) : "l"(p));
    return a;
}
static __device__ __forceinline__ void cp4(uint32_t dst, const float* src) {
    asm volatile("cp.async.ca.shared.global [%0], [%1], 4;" :: "r"(dst), "l"(src));
}
static __device__ __forceinline__ void cp_commit() {
    asm volatile("cp.async.commit_group;" ::: "memory");
}
template <int N>
static __device__ __forceinline__ void cp_wait() {
    asm volatile("cp.async.wait_group %0;" :: "n"(N) : "memory");
}
static __device__ __forceinline__ uint32_t rntf32(float f) {
    uint32_t u;
    asm("cvt.rn.tf32.f32 %0, %1;" : "=r"(u) : "f"(f));
    return u;
}

// mma.sync m16n8k8 tf32: D += A*B  (row.col), fp32 accum
static __device__ __forceinline__ void mma_tf32(float* d, const uint32_t* a, const uint32_t* b) {
    asm volatile(
        "mma.sync.aligned.m16n8k8.row.col.f32.tf32.tf32.f32 "
        "{%0,%1,%2,%3}, {%4,%5,%6,%7}, {%8,%9}, {%0,%1,%2,%3};"
        : "+f"(d[0]), "+f"(d[1]), "+f"(d[2]), "+f"(d[3])
        : "r"(a[0]), "r"(a[1]), "r"(a[2]), "r"(a[3]), "r"(b[0]), "r"(b[1]));
}

// Fragment-order SMEM offsets (floats) for the m16n8k8 tf32 lane maps (R3-verified).
// A tile 128(m) x 32(k):
static __device__ __forceinline__ int offA(int m, int k) {
    int lane = (m & 7) * 4 + (k & 3);
    int j = ((m >> 3) & 1) | (((k >> 2) & 1) << 1);
    return (((m >> 4) * 4 + (k >> 3)) * 128) + lane * 4 + j;
}
// B tile 128(n) x 32(k):
static __device__ __forceinline__ int offB(int n, int k) {
    int lane = (n & 7) * 4 + (k & 3);
    int slot = (k >> 2) & 1;
    return ((((n >> 6) * 8 + ((n >> 3) & 7)) * 4 + (k >> 3)) * 64) + lane * 2 + slot;
}

// ---------------------------------------------------------------------------
// tf32 tensor-core GEMM: cp.async 3-stage pipeline, fragment-order SMEM
// (4B LDGSTS scatter), vector LDS in compute, zero mainloop ALU/cvt except
// CVT_A (A fragments rounded in registers; B operands pre-rounded in GMEM).
// C[m][n] = (sum_k a[m][k]*b[n][k] + bias) * scale
// BM=BN=128, K=256 (8 chunks of 32). 8 warps (4m x 2n), warp tile 32x64.
// ---------------------------------------------------------------------------
template <int TRANS_A, int CVT_A, int BIAS_M>
__global__ void __launch_bounds__(256, 2)
gemm_mma(const float* __restrict__ A, int lda, long sA,
         const float* __restrict__ B, int ldb, long sB,
         float* __restrict__ C, int ldc, long sC,
         const float* __restrict__ bias, float scale) {
    extern __shared__ float sm[];  // 3 stages x (A 4096 | B 4096) floats
    const int tid = threadIdx.x, lane = tid & 31, wid = tid >> 5;
    const int wm = wid & 3, wn = wid >> 2;
    const int bn0 = blockIdx.x * 128, bm0 = blockIdx.y * 128;
    A += sA * blockIdx.z; B += sB * blockIdx.z; C += sC * blockIdx.z;

    const uint32_t smb = smem_u32(sm);

    float d[2][8][4];
#pragma unroll
    for (int mt = 0; mt < 2; mt++)
#pragma unroll
        for (int nt = 0; nt < 8; nt++)
#pragma unroll
            for (int q = 0; q < 4; q++) d[mt][nt][q] = 0.0f;

    auto fill = [&](int slot, int k0) {
        uint32_t abase = smb + slot * 32768;  // bytes
        uint32_t bbase = abase + 16384;
        if (TRANS_A) {
            // src contiguous along m (coalesced); kk = idx>>7
#pragma unroll
            for (int p = 0; p < 16; p++) {
                int idx = tid + p * 256;
                int m = idx & 127, kk = idx >> 7;
                cp4(abase + offA(m, kk) * 4, A + (long)(k0 + kk) * lda + bm0 + m);
            }
        } else {
            // src contiguous along k (coalesced); m = idx>>5
#pragma unroll
            for (int p = 0; p < 16; p++) {
                int idx = tid + p * 256;
                int kk = idx & 31, m = idx >> 5;
                cp4(abase + offA(m, kk) * 4, A + (long)(bm0 + m) * lda + k0 + kk);
            }
        }
#pragma unroll
        for (int p = 0; p < 16; p++) {
            int idx = tid + p * 256;
            int kk = idx & 31, n = idx >> 5;
            cp4(bbase + offB(n, kk) * 4, B + (long)(bn0 + n) * ldb + k0 + kk);
        }
    };

    auto compute = [&](int slot) {
        const float* as = sm + slot * 8192;
        const float* bs = as + 4096;
#pragma unroll
        for (int k8 = 0; k8 < 4; k8++) {
            uint32_t afr[2][4], bfr[8][2];
#pragma unroll
            for (int mt = 0; mt < 2; mt++) {
                uint4 v = *(const uint4*)&as[((wm * 2 + mt) * 4 + k8) * 128 + lane * 4];
                if (CVT_A) {
                    afr[mt][0] = rntf32(__uint_as_float(v.x));
                    afr[mt][1] = rntf32(__uint_as_float(v.y));
                    afr[mt][2] = rntf32(__uint_as_float(v.z));
                    afr[mt][3] = rntf32(__uint_as_float(v.w));
                } else {
                    afr[mt][0] = v.x; afr[mt][1] = v.y; afr[mt][2] = v.z; afr[mt][3] = v.w;
                }
            }
#pragma unroll
            for (int nt = 0; nt < 8; nt++)
                *(uint2*)bfr[nt] = *(const uint2*)&bs[((wn * 8 + nt) * 4 + k8) * 64 + lane * 2];
#pragma unroll
            for (int mt = 0; mt < 2; mt++)
#pragma unroll
                for (int nt = 0; nt < 8; nt++) mma_tf32(d[mt][nt], afr[mt], bfr[nt]);
        }
    };

    fill(0, 0); cp_commit();
    fill(1, 32); cp_commit();

#pragma unroll 1
    for (int kt = 0; kt < 8; kt++) {
        if (kt == 7) cp_wait<0>(); else cp_wait<1>();
        __syncthreads();
        if (kt + 2 < 8) { fill((kt + 2) % 3, (kt + 2) * 32); cp_commit(); }
        compute(kt % 3);
    }

    // epilogue: fragment C map: rows lane>>2 (+8), cols 2*(lane&3)
    const int mrow = bm0 + wm * 32 + (lane >> 2);
    const int ncol = bn0 + wn * 64 + (lane & 3) * 2;
#pragma unroll
    for (int mt = 0; mt < 2; mt++) {
        int m0 = mrow + mt * 16;
#pragma unroll
        for (int nt = 0; nt < 8; nt++) {
            int c = ncol + nt * 8;
            float b0, b1, b2;
            if (BIAS_M) { b0 = bias[m0]; b2 = bias[m0 + 8]; b1 = 0.0f; }
            else { b0 = bias[c]; b1 = bias[c + 1]; b2 = 0.0f; }
            float2 lo, hi;
            if (BIAS_M) {
                lo.x = (d[mt][nt][0] + b0) * scale; lo.y = (d[mt][nt][1] + b0) * scale;
                hi.x = (d[mt][nt][2] + b2) * scale; hi.y = (d[mt][nt][3] + b2) * scale;
            } else {
                lo.x = (d[mt][nt][0] + b0) * scale; lo.y = (d[mt][nt][1] + b1) * scale;
                hi.x = (d[mt][nt][2] + b0) * scale; hi.y = (d[mt][nt][3] + b1) * scale;
            }
            *(float2*)(C + (long)m0 * ldc + c) = lo;
            *(float2*)(C + (long)(m0 + 8) * ldc + c) = hi;
        }
    }
}

// ---------------------------------------------------------------------------
// Pre-round weights to tf32-valid fp32 (RN). grid (64, 2) x 256.
// ---------------------------------------------------------------------------
__global__ void round_weights(const float* __restrict__ Wq, const float* __restrict__ Wo) {
    int i = blockIdx.x * 256 + threadIdx.x;
    const float4 v = ((const float4*)(blockIdx.y ? Wo : Wq))[i];
    float4 r;
    r.x = __uint_as_float(rntf32(v.x));
    r.y = __uint_as_float(rntf32(v.y));
    r.z = __uint_as_float(rntf32(v.z));
    r.w = __uint_as_float(rntf32(v.w));
    ((float4*)(blockIdx.y ? g_Wor : g_Wqr))[i] = r;
}

// ---------------------------------------------------------------------------
// Attention weights: softmax over 9-tap Q-dot window
// ---------------------------------------------------------------------------
__global__ void __launch_bounds__(256) attn_kernel(const float* __restrict__ bq) {
    int b = blockIdx.y;
    int s0 = blockIdx.x * 32;
    __shared__ float Qs[40 * EDIM];

    const float* Qb = g_Q + (long)b * SDIM * EDIM;
    for (int idx = threadIdx.x; idx < 40 * 64; idx += 256) {
        int c = idx >> 6, v = idx & 63;
        int s = s0 - 4 + c;
        float4 val;
        if (s < 0 || s >= SDIM)
            val = ((const float4*)bq)[v];
        else
            val = ((const float4*)(Qb + (long)s * EDIM))[v];
        ((float4*)Qs)[c * 64 + v] = val;
    }
    __syncthreads();

    int w = threadIdx.x >> 5, lane = threadIdx.x & 31;
    const float inv_scale = 1.0f / 24.0f;
#pragma unroll
    for (int i = 0; i < 4; i++) {
        int ls = w * 4 + i;
        int cc = ls + 4;
        float4 c0 = ((float4*)Qs)[cc * 64 + lane];
        float4 c1 = ((float4*)Qs)[cc * 64 + 32 + lane];
        float myd = -1e30f;
#pragma unroll
        for (int l = 0; l < 9; l++) {
            int cl = cc + l - 4;
            float4 q0 = ((float4*)Qs)[cl * 64 + lane];
            float4 q1 = ((float4*)Qs)[cl * 64 + 32 + lane];
            float p = c0.x * q0.x + c0.y * q0.y + c0.z * q0.z + c0.w * q0.w +
                      c1.x * q1.x + c1.y * q1.y + c1.z * q1.z + c1.w * q1.w;
#pragma unroll
            for (int off = 16; off; off >>= 1) p += __shfl_xor_sync(0xffffffffu, p, off);
            if (lane == l) myd = p;
        }
        float eng = myd * inv_scale;
        float m = eng;
#pragma unroll
        for (int off = 16; off; off >>= 1) m = fmaxf(m, __shfl_xor_sync(0xffffffffu, m, off));
        float ev = (lane < 9) ? __expf(eng - m) : 0.0f;
        float sum = ev;
#pragma unroll
        for (int off = 16; off; off >>= 1) sum += __shfl_xor_sync(0xffffffffu, sum, off);
        float a = ev / sum;
        if (lane < 9) g_attn[(long)(b * SDIM + s0 + ls) * 16 + lane] = a;
    }
}

// ---------------------------------------------------------------------------
// Weighted pooling -> pooled^T[b][s][e], tf32-rounded. Division-free loads.
// ---------------------------------------------------------------------------
__global__ void __launch_bounds__(256) pool_kernel(const float* __restrict__ x) {
    int b = blockIdx.z;
    int e0 = blockIdx.y * 32;
    int s0 = blockIdx.x * 128;
    __shared__ float a_sm[128 * 12];   // 9 used of 12 per row
    __shared__ float x_sm[32 * 136];   // cols: s0-4 .. s0+131

    const int tid = threadIdx.x;

    // attn: 128 rows x 3 float4 (12 floats; 9 used)
    if (tid < 128) {
        const float4* ga = (const float4*)(g_attn + ((long)(b * SDIM + s0 + tid) << 4));
        float4 a0 = ga[0], a1 = ga[1], a2 = ga[2];
        float4* dst = (float4*)&a_sm[tid * 12];
        dst[0] = a0; dst[1] = a1; dst[2] = a2;
    }

    // x main tile: 32 x 128 via float4 (shift addressing only)
    const float* xb = x + ((long)b * EDIM + e0) * SDIM;
#pragma unroll
    for (int p = 0; p < 4; p++) {
        int idx = tid + p * 256;
        int e = idx >> 5, s4 = (idx & 31) << 2;
        float4 v = *(const float4*)(xb + (long)e * SDIM + s0 + s4);
        *(float4*)&x_sm[e * 136 + 4 + s4] = v;
    }
    // halo: 32 x 8 (4 left, 4 right)
    {
        int e = tid >> 3, h = tid & 7;
        int j = (h < 4) ? h : (h + 124);      // cols 0-3 and 128-131... (s offsets -4..-1, 124+4..)
        // j maps: h<4 -> col h (s = s0-4+h); h>=4 -> col 128+h (s = s0+124+h)
        j = (h < 4) ? h : (128 + h);
        int s = s0 - 4 + j;
        x_sm[e * 136 + j] = (s >= 0 && s < SDIM) ? xb[(long)e * SDIM + s] : 0.0f;
    }
    __syncthreads();

    int ts = tid & 31, te = tid >> 5;
    float* pt = g_poolT + (long)b * SDIM * EDIM + e0 + te * 4;
#pragma unroll
    for (int si = 0; si < 4; si++) {
        int ls = ts + si * 32;
        float a[9];
#pragma unroll
        for (int l = 0; l < 9; l++) a[l] = a_sm[ls * 12 + l];
        float acc[4];
#pragma unroll
        for (int j = 0; j < 4; j++) {
            int e = te * 4 + j;
            float s = 0.0f;
#pragma unroll
            for (int l = 0; l < 9; l++) s += a[l] * x_sm[e * 136 + ls + l];
            acc[j] = s;
        }
        float4 o;
        o.x = __uint_as_float(rntf32(acc[0]));
        o.y = __uint_as_float(rntf32(acc[1]));
        o.z = __uint_as_float(rntf32(acc[2]));
        o.w = __uint_as_float(rntf32(acc[3]));
        *(float4*)&pt[(long)(s0 + ls) * EDIM] = o;
    }
}

// ---------------------------------------------------------------------------
extern "C" void kernel_launch(void* const* d_in, const int* in_sizes, int n_in,
                              void* d_out, int out_size) {
    const float* x  = (const float*)d_in[0];
    const float* Wq = (const float*)d_in[1];
    const float* bq = (const float*)d_in[2];
    const float* Wo = (const float*)d_in[3];
    const float* bo = (const float*)d_in[4];
    float* out = (float*)d_out;

    float *Qp, *pt, *wqr, *wor;
    cudaGetSymbolAddress((void**)&Qp, g_Q);
    cudaGetSymbolAddress((void**)&pt, g_poolT);
    cudaGetSymbolAddress((void**)&wqr, g_Wqr);
    cudaGetSymbolAddress((void**)&wor, g_Wor);

    const int SMEM = 3 * 32768;
    cudaFuncSetAttribute((const void*)gemm_mma<1, 1, 0>, cudaFuncAttributeMaxDynamicSharedMemorySize, SMEM);
    cudaFuncSetAttribute((const void*)gemm_mma<0, 0, 1>, cudaFuncAttributeMaxDynamicSharedMemorySize, SMEM);

    // 0) round weights to tf32 grid
    round_weights<<<dim3(64, 2), 256>>>(Wq, Wo);

    // 1) Q[b][s][f] = sum_e x[b][e][s]*Wqr[f][e] + bq[f]   (m=s, n=f, k=e)
    gemm_mma<1, 1, 0><<<dim3(2, 16, BDIM), 256, SMEM>>>(
        x, SDIM, (long)EDIM * SDIM,
        wqr, EDIM, 0L,
        Qp, EDIM, (long)SDIM * EDIM,
        bq, 1.0f);

    // 2) attention weights
    attn_kernel<<<dim3(SDIM / 32, BDIM), 256>>>(bq);

    // 3) weighted pooling -> pooled^T[s][e] (tf32-rounded)
    pool_kernel<<<dim3(SDIM / 128, EDIM / 32, BDIM), 256>>>(x);

    // 4) out[b][f][s] = (sum_e Wor[f][e]*pooled^T[s][e] + bo[f]) / 9   (m=f, n=s, k=e)
    gemm_mma<0, 0, 1><<<dim3(16, 2, BDIM), 256, SMEM>>>(
        wor, EDIM, 0L,
        pt, EDIM, (long)SDIM * EDIM,
        out, SDIM, (long)EDIM * SDIM,
        bo, 1.0f / 9.0f);
}

// round 8
// speedup vs baseline: 1.2722x; 1.2722x over previous
#include <cuda_runtime.h>
#include <cstdint>

#define SDIM 2048
#define EDIM 256
#define BDIM 8

__device__ float g_Q[BDIM * SDIM * EDIM];      // Q[b][s][f]
__device__ float g_attn[BDIM * SDIM * 16];     // 9 weights per (b,s), stride 16
__device__ float g_poolT[BDIM * SDIM * EDIM];  // pooled^T [b][s][e], tf32-rounded
__device__ float g_Wqr[EDIM * EDIM];           // Wq tf32-rounded
__device__ float g_Wor[EDIM * EDIM];           // Wo tf32-rounded

static __device__ __forceinline__ uint32_t smem_u32(const void* p) {
    uint32_t a;
    asm("{ .reg .u64 t; cvta.to.shared.u64 t, %1; cvt.u32.u64 %0, t; }" : "=r"(a) : "l"(p));
    return a;
}
static __device__ __forceinline__ void cp4(uint32_t dst, const float* src) {
    asm volatile("cp.async.ca.shared.global [%0], [%1], 4;" :: "r"(dst), "l"(src));
}
static __device__ __forceinline__ void cp16(uint32_t dst, const float* src) {
    asm volatile("cp.async.ca.shared.global [%0], [%1], 16;" :: "r"(dst), "l"(src));
}
static __device__ __forceinline__ void cp_commit() {
    asm volatile("cp.async.commit_group;" ::: "memory");
}
template <int N>
static __device__ __forceinline__ void cp_wait() {
    asm volatile("cp.async.wait_group %0;" :: "n"(N) : "memory");
}
static __device__ __forceinline__ uint32_t rntf32(float f) {
    uint32_t u;
    asm("cvt.rn.tf32.f32 %0, %1;" : "=r"(u) : "f"(f));
    return u;
}

// mma.sync m16n8k8 tf32: D += A*B  (row.col), fp32 accum
static __device__ __forceinline__ void mma_tf32(float* d, const uint32_t* a, const uint32_t* b) {
    asm volatile(
        "mma.sync.aligned.m16n8k8.row.col.f32.tf32.tf32.f32 "
        "{%0,%1,%2,%3}, {%4,%5,%6,%7}, {%8,%9}, {%0,%1,%2,%3};"
        : "+f"(d[0]), "+f"(d[1]), "+f"(d[2]), "+f"(d[3])
        : "r"(a[0]), "r"(a[1]), "r"(a[2]), "r"(a[3]), "r"(b[0]), "r"(b[1]));
}

// ldmatrix x4 (b16 view): for tf32, one m8n8.b16 matrix == 8x4 b32 tile whose
// fragment is lane -> (row=lane>>2, b32col=lane&3) — exactly the mma tf32 map.
#define LDSM_X4(r, a)                                                     \
    asm volatile("ldmatrix.sync.aligned.m8n8.x4.shared.b16 "              \
                 "{%0,%1,%2,%3}, [%4];"                                   \
                 : "=r"((r)[0]), "=r"((r)[1]), "=r"((r)[2]), "=r"((r)[3]) \
                 : "r"(a))

// ---------------------------------------------------------------------------
// tf32 tensor-core GEMM: cp.async 3-stage pipeline, XOR-swizzled K-major SMEM,
// ldmatrix.x4 fragment loads (addr = base ^ (k8<<5)), minimal mainloop ALU.
// C[m][n] = (sum_k a[m][k]*b[n][k] + bias) * scale
// BM=BN=128, K=256 (8 chunks of 32). 8 warps (4m x 2n), warp tile 32x64.
// Tile layout (128 rows x 32 floats): byte(r,k) = r*128 + (((k>>2)^(r&7))<<4) + (k&3)*4
// ---------------------------------------------------------------------------
template <int TRANS_A, int CVT_A, int BIAS_M>
__global__ void __launch_bounds__(256, 2)
gemm_mma(const float* __restrict__ A, int lda, long sA,
         const float* __restrict__ B, int ldb, long sB,
         float* __restrict__ C, int ldc, long sC,
         const float* __restrict__ bias, float scale) {
    extern __shared__ float smraw[];
    const uint32_t smb128 = (smem_u32(smraw) + 127) & ~127u;  // 128-aligned: XOR-safe

    const int tid = threadIdx.x, lane = tid & 31, wid = tid >> 5;
    const int wm = wid & 3, wn = wid >> 2;
    const int bn0 = blockIdx.x * 128, bm0 = blockIdx.y * 128;
    A += sA * blockIdx.z; B += sB * blockIdx.z; C += sC * blockIdx.z;

    float d[2][8][4];
#pragma unroll
    for (int mt = 0; mt < 2; mt++)
#pragma unroll
        for (int nt = 0; nt < 8; nt++)
#pragma unroll
            for (int q = 0; q < 4; q++) d[mt][nt][q] = 0.0f;

    // per-lane ldmatrix base byte offsets (k8 = 0)
    const int r7 = lane & 7;
    uint32_t offAb[2], offBb[4];
#pragma unroll
    for (int mt = 0; mt < 2; mt++) {
        int m = wm * 32 + mt * 16 + r7 + ((lane >> 3) & 1) * 8;
        offAb[mt] = (uint32_t)(m * 128 + (((lane >> 4) ^ r7) << 4));
    }
#pragma unroll
    for (int p = 0; p < 4; p++) {
        int n = wn * 64 + p * 16 + r7 + ((lane >> 4) & 1) * 8;
        offBb[p] = (uint32_t)(n * 128 + ((((lane >> 3) & 1) ^ r7) << 4));
    }

    auto fill = [&](int slot, int k0) {
        uint32_t aS = smb128 + slot * 32768;
        uint32_t bS = aS + 16384;
        if (TRANS_A) {
            // x: contiguous along m -> 4B scatter (coalesced LDG side)
#pragma unroll
            for (int p = 0; p < 16; p++) {
                int idx = tid + p * 256;
                int m = idx & 127, kk = idx >> 7;
                cp4(aS + m * 128 + ((((kk >> 2) ^ (m & 7)) << 4)) + (kk & 3) * 4,
                    A + (long)(k0 + kk) * lda + bm0 + m);
            }
        } else {
#pragma unroll
            for (int p = 0; p < 4; p++) {
                int idx = tid + p * 256;
                int row = idx >> 3, ch = idx & 7;
                cp16(aS + row * 128 + (((ch ^ (row & 7)) << 4)),
                     A + (long)(bm0 + row) * lda + k0 + ch * 4);
            }
        }
#pragma unroll
        for (int p = 0; p < 4; p++) {
            int idx = tid + p * 256;
            int row = idx >> 3, ch = idx & 7;
            cp16(bS + row * 128 + (((ch ^ (row & 7)) << 4)),
                 B + (long)(bn0 + row) * ldb + k0 + ch * 4);
        }
    };

    auto compute = [&](int slot) {
        uint32_t aS = smb128 + slot * 32768;
        uint32_t bS = aS + 16384;
#pragma unroll
        for (int k8 = 0; k8 < 4; k8++) {
            const uint32_t kx = (uint32_t)(k8 << 5);
            uint32_t afr[2][4], bfr[4][4];
#pragma unroll
            for (int mt = 0; mt < 2; mt++) {
                LDSM_X4(afr[mt], (aS + offAb[mt]) ^ kx);
                if (CVT_A) {
#pragma unroll
                    for (int q = 0; q < 4; q++)
                        afr[mt][q] = rntf32(__uint_as_float(afr[mt][q]));
                }
            }
#pragma unroll
            for (int p = 0; p < 4; p++) LDSM_X4(bfr[p], (bS + offBb[p]) ^ kx);
#pragma unroll
            for (int mt = 0; mt < 2; mt++)
#pragma unroll
                for (int p = 0; p < 4; p++) {
                    mma_tf32(d[mt][2 * p],     afr[mt], &bfr[p][0]);
                    mma_tf32(d[mt][2 * p + 1], afr[mt], &bfr[p][2]);
                }
        }
    };

    fill(0, 0); cp_commit();
    fill(1, 32); cp_commit();

#pragma unroll 1
    for (int kt = 0; kt < 8; kt++) {
        if (kt == 7) cp_wait<0>(); else cp_wait<1>();
        __syncthreads();
        if (kt + 2 < 8) { fill((kt + 2) % 3, (kt + 2) * 32); cp_commit(); }
        compute(kt % 3);
    }

    // epilogue (R3-verified C map): rows lane>>2 (+8), cols 2*(lane&3)
    const int mrow = bm0 + wm * 32 + (lane >> 2);
    const int ncol = bn0 + wn * 64 + (lane & 3) * 2;
#pragma unroll
    for (int mt = 0; mt < 2; mt++) {
        int m0 = mrow + mt * 16;
#pragma unroll
        for (int nt = 0; nt < 8; nt++) {
            int c = ncol + nt * 8;
            float b0, b1, b2;
            if (BIAS_M) { b0 = bias[m0]; b2 = bias[m0 + 8]; b1 = 0.0f; }
            else { b0 = bias[c]; b1 = bias[c + 1]; b2 = 0.0f; }
            float2 lo, hi;
            if (BIAS_M) {
                lo.x = (d[mt][nt][0] + b0) * scale; lo.y = (d[mt][nt][1] + b0) * scale;
                hi.x = (d[mt][nt][2] + b2) * scale; hi.y = (d[mt][nt][3] + b2) * scale;
            } else {
                lo.x = (d[mt][nt][0] + b0) * scale; lo.y = (d[mt][nt][1] + b1) * scale;
                hi.x = (d[mt][nt][2] + b0) * scale; hi.y = (d[mt][nt][3] + b1) * scale;
            }
            *(float2*)(C + (long)m0 * ldc + c) = lo;
            *(float2*)(C + (long)(m0 + 8) * ldc + c) = hi;
        }
    }
}

// ---------------------------------------------------------------------------
__global__ void round_weights(const float* __restrict__ Wq, const float* __restrict__ Wo) {
    int i = blockIdx.x * 256 + threadIdx.x;
    const float4 v = ((const float4*)(blockIdx.y ? Wo : Wq))[i];
    float4 r;
    r.x = __uint_as_float(rntf32(v.x));
    r.y = __uint_as_float(rntf32(v.y));
    r.z = __uint_as_float(rntf32(v.z));
    r.w = __uint_as_float(rntf32(v.w));
    ((float4*)(blockIdx.y ? g_Wor : g_Wqr))[i] = r;
}

// ---------------------------------------------------------------------------
// Attention weights: softmax over 9-tap Q-dot window
// ---------------------------------------------------------------------------
__global__ void __launch_bounds__(256) attn_kernel(const float* __restrict__ bq) {
    int b = blockIdx.y;
    int s0 = blockIdx.x * 32;
    __shared__ float Qs[40 * EDIM];

    const float* Qb = g_Q + (long)b * SDIM * EDIM;
    for (int idx = threadIdx.x; idx < 40 * 64; idx += 256) {
        int c = idx >> 6, v = idx & 63;
        int s = s0 - 4 + c;
        float4 val;
        if (s < 0 || s >= SDIM)
            val = ((const float4*)bq)[v];
        else
            val = ((const float4*)(Qb + (long)s * EDIM))[v];
        ((float4*)Qs)[c * 64 + v] = val;
    }
    __syncthreads();

    int w = threadIdx.x >> 5, lane = threadIdx.x & 31;
    const float inv_scale = 1.0f / 24.0f;
#pragma unroll
    for (int i = 0; i < 4; i++) {
        int ls = w * 4 + i;
        int cc = ls + 4;
        float4 c0 = ((float4*)Qs)[cc * 64 + lane];
        float4 c1 = ((float4*)Qs)[cc * 64 + 32 + lane];
        float myd = -1e30f;
#pragma unroll
        for (int l = 0; l < 9; l++) {
            int cl = cc + l - 4;
            float4 q0 = ((float4*)Qs)[cl * 64 + lane];
            float4 q1 = ((float4*)Qs)[cl * 64 + 32 + lane];
            float p = c0.x * q0.x + c0.y * q0.y + c0.z * q0.z + c0.w * q0.w +
                      c1.x * q1.x + c1.y * q1.y + c1.z * q1.z + c1.w * q1.w;
#pragma unroll
            for (int off = 16; off; off >>= 1) p += __shfl_xor_sync(0xffffffffu, p, off);
            if (lane == l) myd = p;
        }
        float eng = myd * inv_scale;
        float m = eng;
#pragma unroll
        for (int off = 16; off; off >>= 1) m = fmaxf(m, __shfl_xor_sync(0xffffffffu, m, off));
        float ev = (lane < 9) ? __expf(eng - m) : 0.0f;
        float sum = ev;
#pragma unroll
        for (int off = 16; off; off >>= 1) sum += __shfl_xor_sync(0xffffffffu, sum, off);
        float a = ev / sum;
        if (lane < 9) g_attn[(long)(b * SDIM + s0 + ls) * 16 + lane] = a;
    }
}

// ---------------------------------------------------------------------------
// Weighted pooling -> pooled^T[b][s][e] tf32-rounded.
// Conflict-free a_sm (stride 13); coalesced poolT store via o_sm staging.
// ---------------------------------------------------------------------------
__global__ void __launch_bounds__(256) pool_kernel(const float* __restrict__ x) {
    int b = blockIdx.z;
    int e0 = blockIdx.y * 32;
    int s0 = blockIdx.x * 128;
    __shared__ float a_sm[128 * 13];
    __shared__ float x_sm[32 * 136];
    __shared__ float o_sm[128 * 36];

    const int tid = threadIdx.x;

    if (tid < 128) {
        const float4* ga = (const float4*)(g_attn + ((long)(b * SDIM + s0 + tid) << 4));
        float4 a0 = ga[0], a1 = ga[1], a2 = ga[2];
        float* dst = &a_sm[tid * 13];
        dst[0] = a0.x; dst[1] = a0.y; dst[2] = a0.z; dst[3] = a0.w;
        dst[4] = a1.x; dst[5] = a1.y; dst[6] = a1.z; dst[7] = a1.w;
        dst[8] = a2.x;
    }

    const float* xb = x + ((long)b * EDIM + e0) * SDIM;
#pragma unroll
    for (int p = 0; p < 4; p++) {
        int idx = tid + p * 256;
        int e = idx >> 5, s4 = (idx & 31) << 2;
        float4 v = *(const float4*)(xb + (long)e * SDIM + s0 + s4);
        *(float4*)&x_sm[e * 136 + 4 + s4] = v;
    }
    {
        int e = tid >> 3, h = tid & 7;
        int j = (h < 4) ? h : (128 + h);
        int s = s0 - 4 + j;
        x_sm[e * 136 + j] = (s >= 0 && s < SDIM) ? xb[(long)e * SDIM + s] : 0.0f;
    }
    __syncthreads();

    int ts = tid & 31, te = tid >> 5;
#pragma unroll
    for (int si = 0; si < 4; si++) {
        int ls = ts + si * 32;
        float a[9];
#pragma unroll
        for (int l = 0; l < 9; l++) a[l] = a_sm[ls * 13 + l];
        float4 o;
        float acc[4];
#pragma unroll
        for (int j = 0; j < 4; j++) {
            int e = te * 4 + j;
            float s = 0.0f;
#pragma unroll
            for (int l = 0; l < 9; l++) s += a[l] * x_sm[e * 136 + ls + l];
            acc[j] = s;
        }
        o.x = acc[0]; o.y = acc[1]; o.z = acc[2]; o.w = acc[3];
        *(float4*)&o_sm[ls * 36 + te * 4] = o;
    }
    __syncthreads();

    float* ptb = g_poolT + (long)b * SDIM * EDIM + e0;
#pragma unroll
    for (int p = 0; p < 4; p++) {
        int idx = tid + p * 256;
        int s = idx >> 3, e4 = (idx & 7) << 2;
        float4 v = *(const float4*)&o_sm[s * 36 + e4];
        float4 r;
        r.x = __uint_as_float(rntf32(v.x));
        r.y = __uint_as_float(rntf32(v.y));
        r.z = __uint_as_float(rntf32(v.z));
        r.w = __uint_as_float(rntf32(v.w));
        *(float4*)(ptb + (long)(s0 + s) * EDIM + e4) = r;
    }
}

// ---------------------------------------------------------------------------
extern "C" void kernel_launch(void* const* d_in, const int* in_sizes, int n_in,
                              void* d_out, int out_size) {
    const float* x  = (const float*)d_in[0];
    const float* Wq = (const float*)d_in[1];
    const float* bq = (const float*)d_in[2];
    const float* Wo = (const float*)d_in[3];
    const float* bo = (const float*)d_in[4];
    float* out = (float*)d_out;

    float *Qp, *pt, *wqr, *wor;
    cudaGetSymbolAddress((void**)&Qp, g_Q);
    cudaGetSymbolAddress((void**)&pt, g_poolT);
    cudaGetSymbolAddress((void**)&wqr, g_Wqr);
    cudaGetSymbolAddress((void**)&wor, g_Wor);

    const int SMEM = 3 * 32768 + 128;
    cudaFuncSetAttribute((const void*)gemm_mma<1, 1, 0>, cudaFuncAttributeMaxDynamicSharedMemorySize, SMEM);
    cudaFuncSetAttribute((const void*)gemm_mma<0, 0, 1>, cudaFuncAttributeMaxDynamicSharedMemorySize, SMEM);

    // 0) round weights to tf32 grid
    round_weights<<<dim3(64, 2), 256>>>(Wq, Wo);

    // 1) Q[b][s][f] = sum_e x[b][e][s]*Wqr[f][e] + bq[f]   (m=s, n=f, k=e)
    gemm_mma<1, 1, 0><<<dim3(2, 16, BDIM), 256, SMEM>>>(
        x, SDIM, (long)EDIM * SDIM,
        wqr, EDIM, 0L,
        Qp, EDIM, (long)SDIM * EDIM,
        bq, 1.0f);

    // 2) attention weights
    attn_kernel<<<dim3(SDIM / 32, BDIM), 256>>>(bq);

    // 3) weighted pooling -> pooled^T[s][e] (tf32-rounded)
    pool_kernel<<<dim3(SDIM / 128, EDIM / 32, BDIM), 256>>>(x);

    // 4) out[b][f][s] = (sum_e Wor[f][e]*pooled^T[s][e] + bo[f]) / 9   (m=f, n=s, k=e)
    gemm_mma<0, 0, 1><<<dim3(16, 2, BDIM), 256, SMEM>>>(
        wor, EDIM, 0L,
        pt, EDIM, (long)SDIM * EDIM,
        out, SDIM, (long)EDIM * SDIM,
        bo, 1.0f / 9.0f);
}